// round 2
// baseline (speedup 1.0000x reference)
#include <cuda_runtime.h>

// BSplineEncoder: out[n, c] = b[c] + sum_j basis_j(x[n]) * W[c, j]
// Cubic clamped-uniform B-spline, 10 basis fns, 7 spans on [0,1].
// Only 4 basis values are nonzero per x (span j .. j+3).
//
// HBM-store-bound: 536 MB output. Warp-per-x, float4-per-lane coalesced
// streaming stores; basis computed once per x (phase 1), broadcast via smem.

#define N_BASIS 10
#define CH      128
#define TILE    256
#define NTHREADS 256

__global__ __launch_bounds__(NTHREADS, 8)
void bspline_encoder_kernel(const float* __restrict__ x,
                            const float* __restrict__ W,   // [128, 10] row-major
                            const float* __restrict__ bias, // [128]
                            float* __restrict__ out,        // [n, 128]
                            int n)
{
    __shared__ float  sW[N_BASIS][CH];   // transposed W: sW[j][c]
    __shared__ float4 sBv[CH / 4];       // bias as float4
    __shared__ float4 sBas[TILE];        // {B0,B1,B2,B3} per x
    __shared__ int    sIdx[TILE];        // span j per x

    const int tid = threadIdx.x;

    // ---- Load W transposed + bias into shared (one-time, L2-resident) ----
    for (int idx = tid; idx < N_BASIS * CH; idx += NTHREADS) {
        int c  = idx / N_BASIS;
        int jb = idx - c * N_BASIS;
        sW[jb][c] = W[idx];               // W[c*10 + jb]
    }
    if (tid < CH) ((float*)sBv)[tid] = bias[tid];

    const int base = blockIdx.x * TILE;

    // ---- Phase 1: one thread per x, Cox-de Boor (degree 3) ----
    {
        int t = base + tid;
        if (t < n) {
            float xv = x[t];
            xv = fminf(fmaxf(xv, 1e-9f), 1.0f);
            const float inv7 = 1.0f / 7.0f;
            int j = (int)(xv * 7.0f);
            j = min(j, 6);

            // knots around span i = j+3 (clamped at both ends)
            float left1  = xv - (float)j * inv7;
            float left2  = xv - (float)max(j - 1, 0) * inv7;
            float left3  = xv - (float)max(j - 2, 0) * inv7;
            float right1 = (float)min(j + 1, 7) * inv7 - xv;
            float right2 = (float)min(j + 2, 7) * inv7 - xv;
            float right3 = (float)min(j + 3, 7) * inv7 - xv;

            float N0 = 1.0f, N1, N2, N3, saved, temp;
            // d = 1
            temp = N0 / (right1 + left1);
            N0 = right1 * temp;
            N1 = left1 * temp;
            // d = 2
            temp = N0 / (right1 + left2);
            N0 = right1 * temp;  saved = left2 * temp;
            temp = N1 / (right2 + left1);
            N1 = saved + right2 * temp;  saved = left1 * temp;
            N2 = saved;
            // d = 3
            temp = N0 / (right1 + left3);
            N0 = right1 * temp;  saved = left3 * temp;
            temp = N1 / (right2 + left2);
            N1 = saved + right2 * temp;  saved = left2 * temp;
            temp = N2 / (right3 + left1);
            N2 = saved + right3 * temp;  saved = left1 * temp;
            N3 = saved;

            // Reference uses strict x < knot indicators: basis == 0 at x == 1.0
            if (xv >= 1.0f) { N0 = N1 = N2 = N3 = 0.0f; }

            sBas[tid] = make_float4(N0, N1, N2, N3);
            sIdx[tid] = j;
        } else {
            sBas[tid] = make_float4(0.f, 0.f, 0.f, 0.f);
            sIdx[tid] = 0;
        }
    }
    __syncthreads();

    // ---- Phase 2: warp-per-x, float4-per-lane, streaming stores ----
    const int warp = tid >> 5;
    const int lane = tid & 31;
    const float4 bv = sBv[lane];
    float* outBase = out + (size_t)base * CH;
    const float4* sW4 = (const float4*)sW;   // [N_BASIS][32]

    const int lim = min(TILE, n - base);
    #pragma unroll 4
    for (int t = warp; t < lim; t += 8) {
        float4 Bv = sBas[t];          // LDS.128 broadcast
        int    j  = sIdx[t];          // LDS broadcast
        float4 w0 = sW4[(j    ) * 32 + lane];
        float4 w1 = sW4[(j + 1) * 32 + lane];
        float4 w2 = sW4[(j + 2) * 32 + lane];
        float4 w3 = sW4[(j + 3) * 32 + lane];

        float4 o;
        o.x = fmaf(Bv.x, w0.x, fmaf(Bv.y, w1.x, fmaf(Bv.z, w2.x, fmaf(Bv.w, w3.x, bv.x))));
        o.y = fmaf(Bv.x, w0.y, fmaf(Bv.y, w1.y, fmaf(Bv.z, w2.y, fmaf(Bv.w, w3.y, bv.y))));
        o.z = fmaf(Bv.x, w0.z, fmaf(Bv.y, w1.z, fmaf(Bv.z, w2.z, fmaf(Bv.w, w3.z, bv.z))));
        o.w = fmaf(Bv.x, w0.w, fmaf(Bv.y, w1.w, fmaf(Bv.z, w2.w, fmaf(Bv.w, w3.w, bv.w))));

        // streaming store: output far exceeds L2, no reuse
        __stcs(reinterpret_cast<float4*>(outBase + (size_t)t * CH + lane * 4), o);
    }
}

extern "C" void kernel_launch(void* const* d_in, const int* in_sizes, int n_in,
                              void* d_out, int out_size) {
    const float* x    = (const float*)d_in[0];
    const float* W    = (const float*)d_in[1];
    const float* bias = (const float*)d_in[2];
    float* out = (float*)d_out;

    int n = in_sizes[0];                    // 512 * 2048 = 1,048,576
    int blocks = (n + TILE - 1) / TILE;     // 4096
    bspline_encoder_kernel<<<blocks, NTHREADS>>>(x, W, bias, out, n);
}

// round 3
// speedup vs baseline: 1.3425x; 1.3425x over previous
#include <cuda_runtime.h>

// BSplineEncoder: out[n, c] = b[c] + sum_k basis_k(x[n]) * W[c, k]
// Cubic clamped-uniform B-spline, 10 basis fns, 7 spans on [0,1].
//
// R2 analysis: L1TEX 94% (smem W loads) was binding, DRAM 56%. This version
// keeps W in per-lane registers (4 channels x 10 basis), uses dense 10-term
// dot product with packed fma.rn.f32x2 (2x fp32 pipe), and only broadcasts a
// duplicated 10-vector basis (5x LDS.128) per x. Target: DRAM-store-bound.

#define N_BASIS 10
#define CH      128
#define TILE    256
#define NTHREADS 256

using u64 = unsigned long long;

__device__ __forceinline__ u64 pack2(float lo, float hi) {
    u64 d; asm("mov.b64 %0, {%1, %2};" : "=l"(d) : "f"(lo), "f"(hi)); return d;
}
__device__ __forceinline__ void unpack2(u64 v, float& lo, float& hi) {
    asm("mov.b64 {%0, %1}, %2;" : "=f"(lo), "=f"(hi) : "l"(v));
}
// packed fp32x2 FMA: d = a*b + c on both halves (Blackwell 2x fp32 path)
__device__ __forceinline__ u64 ffma2(u64 a, u64 b, u64 c) {
    u64 d; asm("fma.rn.f32x2 %0, %1, %2, %3;" : "=l"(d) : "l"(a), "l"(b), "l"(c)); return d;
}

__global__ __launch_bounds__(NTHREADS)
void bspline_encoder_kernel(const float* __restrict__ x,
                            const float* __restrict__ W,    // [128, 10] row-major
                            const float* __restrict__ bias, // [128]
                            float* __restrict__ out,        // [n, 128]
                            int n)
{
    __shared__ float2 sB[TILE][N_BASIS];     // duplicated basis {Bk,Bk} per x (80 B rows, 16B-aligned)
    __shared__ float  sWf[CH * N_BASIS];     // staged W for conflict-cheap register fill
    __shared__ float  sBias[CH];

    const int tid  = threadIdx.x;
    const int warp = tid >> 5;
    const int lane = tid & 31;
    const int base = blockIdx.x * TILE;

    // ---- Stage W + bias into smem (coalesced, one-time) ----
    for (int idx = tid; idx < CH * N_BASIS; idx += NTHREADS) sWf[idx] = W[idx];
    if (tid < CH) sBias[tid] = bias[tid];

    // ---- Phase 1: one thread per x, Cox-de Boor (degree 3), scatter into dense 10-vec ----
    {
        int t = base + tid;
        const float2 z2 = make_float2(0.f, 0.f);
        #pragma unroll
        for (int k = 0; k < N_BASIS; k++) sB[tid][k] = z2;

        if (t < n) {
            float xv = x[t];
            xv = fminf(fmaxf(xv, 1e-9f), 1.0f);
            const float inv7 = 1.0f / 7.0f;
            int j = (int)(xv * 7.0f);
            j = min(j, 6);

            float left1  = xv - (float)j * inv7;
            float left2  = xv - (float)max(j - 1, 0) * inv7;
            float left3  = xv - (float)max(j - 2, 0) * inv7;
            float right1 = (float)min(j + 1, 7) * inv7 - xv;
            float right2 = (float)min(j + 2, 7) * inv7 - xv;
            float right3 = (float)min(j + 3, 7) * inv7 - xv;

            float N0 = 1.0f, N1, N2, N3, saved, temp;
            // d = 1
            temp = N0 / (right1 + left1);
            N0 = right1 * temp;
            N1 = left1 * temp;
            // d = 2
            temp = N0 / (right1 + left2);
            N0 = right1 * temp;  saved = left2 * temp;
            temp = N1 / (right2 + left1);
            N1 = saved + right2 * temp;
            N2 = left1 * temp;
            // d = 3
            temp = N0 / (right1 + left3);
            N0 = right1 * temp;  saved = left3 * temp;
            temp = N1 / (right2 + left2);
            N1 = saved + right2 * temp;  saved = left2 * temp;
            temp = N2 / (right3 + left1);
            N2 = saved + right3 * temp;
            N3 = left1 * temp;

            // Reference uses strict x < knot indicators: basis == 0 at x == 1.0
            if (xv < 1.0f) {
                sB[tid][j + 0] = make_float2(N0, N0);
                sB[tid][j + 1] = make_float2(N1, N1);
                sB[tid][j + 2] = make_float2(N2, N2);
                sB[tid][j + 3] = make_float2(N3, N3);
            }
        }
    }
    __syncthreads();

    // ---- Fill per-lane W registers: 4 channels (c = 4*lane + 0..3), pairs packed f32x2 ----
    u64 wlo[N_BASIS], whi[N_BASIS];
    {
        const float* w0 = sWf + (lane * 4 + 0) * N_BASIS;
        const float* w1 = sWf + (lane * 4 + 1) * N_BASIS;
        const float* w2 = sWf + (lane * 4 + 2) * N_BASIS;
        const float* w3 = sWf + (lane * 4 + 3) * N_BASIS;
        #pragma unroll
        for (int k = 0; k < N_BASIS; k++) {
            wlo[k] = pack2(w0[k], w1[k]);
            whi[k] = pack2(w2[k], w3[k]);
        }
    }
    const u64 blo = pack2(sBias[lane * 4 + 0], sBias[lane * 4 + 1]);
    const u64 bhi = pack2(sBias[lane * 4 + 2], sBias[lane * 4 + 3]);

    // ---- Phase 2: warp-per-x, 5 broadcast LDS.128 + 20 FFMA2 + 1 STG.128 ----
    const int lim = min(TILE, n - base);
    float* outLane = out + (size_t)base * CH + lane * 4;

    #pragma unroll 4
    for (int t = warp; t < lim; t += 8) {
        const ulonglong2* r = reinterpret_cast<const ulonglong2*>(&sB[t][0]);
        ulonglong2 a0 = r[0];   // {B0,B0},{B1,B1}
        ulonglong2 a1 = r[1];   // {B2,B2},{B3,B3}
        ulonglong2 a2 = r[2];   // {B4,B4},{B5,B5}
        ulonglong2 a3 = r[3];   // {B6,B6},{B7,B7}
        ulonglong2 a4 = r[4];   // {B8,B8},{B9,B9}

        u64 acc_lo = blo, acc_hi = bhi;
        acc_lo = ffma2(a0.x, wlo[0], acc_lo);  acc_hi = ffma2(a0.x, whi[0], acc_hi);
        acc_lo = ffma2(a0.y, wlo[1], acc_lo);  acc_hi = ffma2(a0.y, whi[1], acc_hi);
        acc_lo = ffma2(a1.x, wlo[2], acc_lo);  acc_hi = ffma2(a1.x, whi[2], acc_hi);
        acc_lo = ffma2(a1.y, wlo[3], acc_lo);  acc_hi = ffma2(a1.y, whi[3], acc_hi);
        acc_lo = ffma2(a2.x, wlo[4], acc_lo);  acc_hi = ffma2(a2.x, whi[4], acc_hi);
        acc_lo = ffma2(a2.y, wlo[5], acc_lo);  acc_hi = ffma2(a2.y, whi[5], acc_hi);
        acc_lo = ffma2(a3.x, wlo[6], acc_lo);  acc_hi = ffma2(a3.x, whi[6], acc_hi);
        acc_lo = ffma2(a3.y, wlo[7], acc_lo);  acc_hi = ffma2(a3.y, whi[7], acc_hi);
        acc_lo = ffma2(a4.x, wlo[8], acc_lo);  acc_hi = ffma2(a4.x, whi[8], acc_hi);
        acc_lo = ffma2(a4.y, wlo[9], acc_lo);  acc_hi = ffma2(a4.y, whi[9], acc_hi);

        float4 o;
        unpack2(acc_lo, o.x, o.y);
        unpack2(acc_hi, o.z, o.w);
        // streaming store: output far exceeds L2, no reuse
        __stcs(reinterpret_cast<float4*>(outLane + (size_t)t * CH), o);
    }
}

extern "C" void kernel_launch(void* const* d_in, const int* in_sizes, int n_in,
                              void* d_out, int out_size) {
    const float* x    = (const float*)d_in[0];
    const float* W    = (const float*)d_in[1];
    const float* bias = (const float*)d_in[2];
    float* out = (float*)d_out;

    int n = in_sizes[0];                    // 512 * 2048 = 1,048,576
    int blocks = (n + TILE - 1) / TILE;     // 4096
    bspline_encoder_kernel<<<blocks, NTHREADS>>>(x, W, bias, out, n);
}

// round 4
// speedup vs baseline: 1.4440x; 1.0756x over previous
#include <cuda_runtime.h>

// BSplineEncoder: out[n, c] = b[c] + sum_k basis_k(x[n]) * W[c, k]
// Cubic clamped-uniform B-spline, 10 basis fns, 7 spans on [0,1].
//
// R3 analysis: DRAM 72.4%, L1 75.3% (co-binding). This version cuts phase-2
// smem traffic from 5 LDS.128 to 3 LDS.128 per x by storing the basis
// non-duplicated (10 floats, 48B padded row) and duplicating into f32x2
// register pairs with cheap ALU movs (ALU pipe was at 9.3%).

#define N_BASIS 10
#define BAS_PAD 12            // 10 floats padded to 12 (48 B, 16B-aligned rows)
#define CH      128
#define TILE    256
#define NTHREADS 256

using u64 = unsigned long long;

__device__ __forceinline__ u64 pack2(float lo, float hi) {
    u64 d; asm("mov.b64 %0, {%1, %2};" : "=l"(d) : "f"(lo), "f"(hi)); return d;
}
__device__ __forceinline__ void unpack2(u64 v, float& lo, float& hi) {
    asm("mov.b64 {%0, %1}, %2;" : "=f"(lo), "=f"(hi) : "l"(v));
}
// packed fp32x2 FMA: d = a*b + c on both halves (Blackwell 2x fp32 path)
__device__ __forceinline__ u64 ffma2(u64 a, u64 b, u64 c) {
    u64 d; asm("fma.rn.f32x2 %0, %1, %2, %3;" : "=l"(d) : "l"(a), "l"(b), "l"(c)); return d;
}

__global__ __launch_bounds__(NTHREADS)
void bspline_encoder_kernel(const float* __restrict__ x,
                            const float* __restrict__ W,    // [128, 10] row-major
                            const float* __restrict__ bias, // [128]
                            float* __restrict__ out,        // [n, 128]
                            int n)
{
    __shared__ float sB[TILE][BAS_PAD];   // non-duplicated basis, 48 B rows
    __shared__ float sWf[CH * N_BASIS];   // staged W for conflict-cheap register fill
    __shared__ float sBias[CH];

    const int tid  = threadIdx.x;
    const int warp = tid >> 5;
    const int lane = tid & 31;
    const int base = blockIdx.x * TILE;

    // ---- Stage W + bias into smem (coalesced, one-time) ----
    for (int idx = tid; idx < CH * N_BASIS; idx += NTHREADS) sWf[idx] = W[idx];
    if (tid < CH) sBias[tid] = bias[tid];

    // ---- Phase 1: one thread per x, Cox-de Boor (degree 3), scatter into dense 10-vec ----
    {
        int t = base + tid;
        #pragma unroll
        for (int k = 0; k < BAS_PAD; k++) sB[tid][k] = 0.0f;

        if (t < n) {
            float xv = x[t];
            xv = fminf(fmaxf(xv, 1e-9f), 1.0f);
            const float inv7 = 1.0f / 7.0f;
            int j = (int)(xv * 7.0f);
            j = min(j, 6);

            float left1  = xv - (float)j * inv7;
            float left2  = xv - (float)max(j - 1, 0) * inv7;
            float left3  = xv - (float)max(j - 2, 0) * inv7;
            float right1 = (float)min(j + 1, 7) * inv7 - xv;
            float right2 = (float)min(j + 2, 7) * inv7 - xv;
            float right3 = (float)min(j + 3, 7) * inv7 - xv;

            float N0 = 1.0f, N1, N2, N3, saved, temp;
            // d = 1
            temp = N0 / (right1 + left1);
            N0 = right1 * temp;
            N1 = left1 * temp;
            // d = 2
            temp = N0 / (right1 + left2);
            N0 = right1 * temp;  saved = left2 * temp;
            temp = N1 / (right2 + left1);
            N1 = saved + right2 * temp;
            N2 = left1 * temp;
            // d = 3
            temp = N0 / (right1 + left3);
            N0 = right1 * temp;  saved = left3 * temp;
            temp = N1 / (right2 + left2);
            N1 = saved + right2 * temp;  saved = left2 * temp;
            temp = N2 / (right3 + left1);
            N2 = saved + right3 * temp;
            N3 = left1 * temp;

            // Reference uses strict x < knot indicators: basis == 0 at x == 1.0
            if (xv < 1.0f) {
                sB[tid][j + 0] = N0;
                sB[tid][j + 1] = N1;
                sB[tid][j + 2] = N2;
                sB[tid][j + 3] = N3;
            }
        }
    }
    __syncthreads();

    // ---- Fill per-lane W registers: 4 channels (c = 4*lane + 0..3), pairs packed f32x2 ----
    u64 wlo[N_BASIS], whi[N_BASIS];
    {
        const float* w0 = sWf + (lane * 4 + 0) * N_BASIS;
        const float* w1 = sWf + (lane * 4 + 1) * N_BASIS;
        const float* w2 = sWf + (lane * 4 + 2) * N_BASIS;
        const float* w3 = sWf + (lane * 4 + 3) * N_BASIS;
        #pragma unroll
        for (int k = 0; k < N_BASIS; k++) {
            wlo[k] = pack2(w0[k], w1[k]);
            whi[k] = pack2(w2[k], w3[k]);
        }
    }
    const u64 blo = pack2(sBias[lane * 4 + 0], sBias[lane * 4 + 1]);
    const u64 bhi = pack2(sBias[lane * 4 + 2], sBias[lane * 4 + 3]);

    // ---- Phase 2: warp-per-x, 3 broadcast LDS.128 + 10 dup movs + 20 FFMA2 + 1 STG.128 ----
    const int lim = min(TILE, n - base);
    float* outLane = out + (size_t)base * CH + lane * 4;

    #pragma unroll 4
    for (int t = warp; t < lim; t += 8) {
        const float4* r = reinterpret_cast<const float4*>(&sB[t][0]);
        float4 b0 = r[0];   // B0..B3
        float4 b1 = r[1];   // B4..B7
        float4 b2 = r[2];   // B8, B9, pad, pad

        u64 acc_lo = blo, acc_hi = bhi;
        u64 a;
        a = pack2(b0.x, b0.x); acc_lo = ffma2(a, wlo[0], acc_lo); acc_hi = ffma2(a, whi[0], acc_hi);
        a = pack2(b0.y, b0.y); acc_lo = ffma2(a, wlo[1], acc_lo); acc_hi = ffma2(a, whi[1], acc_hi);
        a = pack2(b0.z, b0.z); acc_lo = ffma2(a, wlo[2], acc_lo); acc_hi = ffma2(a, whi[2], acc_hi);
        a = pack2(b0.w, b0.w); acc_lo = ffma2(a, wlo[3], acc_lo); acc_hi = ffma2(a, whi[3], acc_hi);
        a = pack2(b1.x, b1.x); acc_lo = ffma2(a, wlo[4], acc_lo); acc_hi = ffma2(a, whi[4], acc_hi);
        a = pack2(b1.y, b1.y); acc_lo = ffma2(a, wlo[5], acc_lo); acc_hi = ffma2(a, whi[5], acc_hi);
        a = pack2(b1.z, b1.z); acc_lo = ffma2(a, wlo[6], acc_lo); acc_hi = ffma2(a, whi[6], acc_hi);
        a = pack2(b1.w, b1.w); acc_lo = ffma2(a, wlo[7], acc_lo); acc_hi = ffma2(a, whi[7], acc_hi);
        a = pack2(b2.x, b2.x); acc_lo = ffma2(a, wlo[8], acc_lo); acc_hi = ffma2(a, whi[8], acc_hi);
        a = pack2(b2.y, b2.y); acc_lo = ffma2(a, wlo[9], acc_lo); acc_hi = ffma2(a, whi[9], acc_hi);

        float4 o;
        unpack2(acc_lo, o.x, o.y);
        unpack2(acc_hi, o.z, o.w);
        // streaming store: output far exceeds L2, no reuse
        __stcs(reinterpret_cast<float4*>(outLane + (size_t)t * CH), o);
    }
}

extern "C" void kernel_launch(void* const* d_in, const int* in_sizes, int n_in,
                              void* d_out, int out_size) {
    const float* x    = (const float*)d_in[0];
    const float* W    = (const float*)d_in[1];
    const float* bias = (const float*)d_in[2];
    float* out = (float*)d_out;

    int n = in_sizes[0];                    // 512 * 2048 = 1,048,576
    int blocks = (n + TILE - 1) / TILE;     // 4096
    bspline_encoder_kernel<<<blocks, NTHREADS>>>(x, W, bias, out, n);
}